// round 11
// baseline (speedup 1.0000x reference)
#include <cuda_runtime.h>

#define B_   2
#define N_   2048
#define H_   8
#define DH_  64
#define BH_  16
#define QMOD 513

// Scratch (device globals; no runtime allocation allowed).
__device__ float g_q[BH_ * N_ * DH_];
__device__ float g_k[BH_ * N_ * DH_];
__device__ float g_v[BH_ * N_ * DH_];
__device__ float g_t[BH_ * N_ * DH_];
__device__ float g_cat[B_ * N_ * H_ * 2 * DH_];   // [b][n][h][128]

// ---------------------------------------------------------------------------
// TF32 helpers
// ---------------------------------------------------------------------------
__device__ __forceinline__ float to_tf32(float x) {
    float r;
    asm("cvt.rna.tf32.f32 %0, %1;" : "=f"(r) : "f"(x));
    return r;
}
__device__ __forceinline__ float4 cvt4(float4 v) {
    v.x = to_tf32(v.x); v.y = to_tf32(v.y);
    v.z = to_tf32(v.z); v.w = to_tf32(v.w);
    return v;
}

// D = A(16x8,row) * B(8x8,col) + C, tf32 inputs, f32 accumulate.
__device__ __forceinline__ void mma8(float4& d, const unsigned* a,
                                     const unsigned* b, const float4& c) {
    asm volatile(
        "mma.sync.aligned.m16n8k8.row.col.f32.tf32.tf32.f32 "
        "{%0,%1,%2,%3}, {%4,%5,%6,%7}, {%8,%9}, {%10,%11,%12,%13};\n"
        : "=f"(d.x), "=f"(d.y), "=f"(d.z), "=f"(d.w)
        : "r"(a[0]), "r"(a[1]), "r"(a[2]), "r"(a[3]),
          "r"(b[0]), "r"(b[1]),
          "f"(c.x), "f"(c.y), "f"(c.z), "f"(c.w));
}

// ---------------------------------------------------------------------------
// Kernel 1: qkvt = X[4096,512] @ W_qkv[512,2048]  (tf32 MMA, 128x64 tile,
// double-buffered SMEM + register prefetch, 2 CTAs/SM).
// ---------------------------------------------------------------------------
__global__ __launch_bounds__(256, 2) void k_gemm_qkv(const float* __restrict__ X,
                                                     const float* __restrict__ W)
{
    __shared__ float As[2][128][36];
    __shared__ float Bs[2][32][72];
    const int tid  = threadIdx.x;
    const int lane = tid & 31, warp = tid >> 5;
    const int gid  = lane >> 2, tig = lane & 3;
    const int row0 = blockIdx.y << 7, col0 = blockIdx.x << 6;
    const int wm = (warp & 3) << 5;     // 0/32/64/96
    const int wn = (warp >> 2) << 5;    // 0/32

    float4 acc[2][4];
#pragma unroll
    for (int i = 0; i < 2; ++i)
#pragma unroll
        for (int j = 0; j < 4; ++j) acc[i][j] = make_float4(0.f, 0.f, 0.f, 0.f);

    const int ar_ = tid >> 3, ac_ = (tid & 7) << 2;   // A: 32 rows/pass x4
    const int br_ = tid >> 4, bc_ = (tid & 15) << 2;  // B: 16 rows/pass x2

    float4 ra[4], rb[2];
#pragma unroll
    for (int p = 0; p < 4; ++p)
        ra[p] = *(const float4*)(X + (row0 + ar_ + (p << 5)) * 512 + ac_);
#pragma unroll
    for (int p = 0; p < 2; ++p)
        rb[p] = *(const float4*)(W + (br_ + (p << 4)) * 2048 + col0 + bc_);
#pragma unroll
    for (int p = 0; p < 4; ++p)
        *(float4*)&As[0][ar_ + (p << 5)][ac_] = cvt4(ra[p]);
#pragma unroll
    for (int p = 0; p < 2; ++p)
        *(float4*)&Bs[0][br_ + (p << 4)][bc_] = cvt4(rb[p]);
    __syncthreads();

    int buf = 0;
    for (int k0 = 0; k0 < 512; k0 += 32) {
        const bool nxt = (k0 + 32) < 512;
        if (nxt) {
#pragma unroll
            for (int p = 0; p < 4; ++p)
                ra[p] = *(const float4*)(X + (row0 + ar_ + (p << 5)) * 512
                                         + k0 + 32 + ac_);
#pragma unroll
            for (int p = 0; p < 2; ++p)
                rb[p] = *(const float4*)(W + (k0 + 32 + br_ + (p << 4)) * 2048
                                         + col0 + bc_);
        }
        float (*Ac)[36] = As[buf];
        float (*Bc)[72] = Bs[buf];
#pragma unroll
        for (int ks = 0; ks < 4; ++ks) {
            const int kk = ks << 3;
            unsigned a[2][4], b[4][2];
#pragma unroll
            for (int mt = 0; mt < 2; ++mt) {
                int r = wm + (mt << 4) + gid;
                a[mt][0] = __float_as_uint(Ac[r][kk + tig]);
                a[mt][1] = __float_as_uint(Ac[r + 8][kk + tig]);
                a[mt][2] = __float_as_uint(Ac[r][kk + tig + 4]);
                a[mt][3] = __float_as_uint(Ac[r + 8][kk + tig + 4]);
            }
#pragma unroll
            for (int nt = 0; nt < 4; ++nt) {
                int c = wn + (nt << 3) + gid;
                b[nt][0] = __float_as_uint(Bc[kk + tig][c]);
                b[nt][1] = __float_as_uint(Bc[kk + tig + 4][c]);
            }
#pragma unroll
            for (int mt = 0; mt < 2; ++mt)
#pragma unroll
                for (int nt = 0; nt < 4; ++nt)
                    mma8(acc[mt][nt], a[mt], b[nt], acc[mt][nt]);
        }
        if (nxt) {
            float (*An)[36] = As[buf ^ 1];
            float (*Bn)[72] = Bs[buf ^ 1];
#pragma unroll
            for (int p = 0; p < 4; ++p)
                *(float4*)&An[ar_ + (p << 5)][ac_] = cvt4(ra[p]);
#pragma unroll
            for (int p = 0; p < 2; ++p)
                *(float4*)&Bn[br_ + (p << 4)][bc_] = cvt4(rb[p]);
        }
        __syncthreads();
        buf ^= 1;
    }

    // Scatter epilogue: whole 64-col tile lies in one section+head block.
    const int sec = col0 >> 9;
    const int h   = (col0 >> 6) & 7;
    float* dst = (sec == 0) ? g_q : (sec == 1) ? g_k : (sec == 2) ? g_v : g_t;
#pragma unroll
    for (int mt = 0; mt < 2; ++mt) {
        int gr0 = row0 + wm + (mt << 4) + gid;
        int gr1 = gr0 + 8;
        int b0i = gr0 >> 11, n0i = gr0 & (N_ - 1);
        int b1i = gr1 >> 11, n1i = gr1 & (N_ - 1);
#pragma unroll
        for (int nt = 0; nt < 4; ++nt) {
            int d = wn + (nt << 3) + (tig << 1);
            *(float2*)(dst + (((b0i << 3) | h) * N_ + n0i) * DH_ + d)
                = make_float2(acc[mt][nt].x, acc[mt][nt].y);
            *(float2*)(dst + (((b1i << 3) | h) * N_ + n1i) * DH_ + d)
                = make_float2(acc[mt][nt].z, acc[mt][nt].w);
        }
    }
}

// ---------------------------------------------------------------------------
// Kernel 2: flash attention (attn1), tf32 MMA, K-chunk 64, single-buffered
// K/V (cross-CTA overlap at 3 CTAs/SM hides load latency). 128 threads.
// ---------------------------------------------------------------------------
__global__ __launch_bounds__(128, 3) void k_attn()
{
    __shared__ float Qs[64][68];   // A operand [q][d]
    __shared__ float Ks[64][68];   // B operand for S: [token][d]
    __shared__ float Vs[64][72];   // B operand for PV: [token][d]
    __shared__ float Ps[64][68];   // A operand for PV: [q][token]

    const int tid  = threadIdx.x;
    const int lane = tid & 31, warp = tid >> 5;
    const int gid  = lane >> 2, tig = lane & 3;
    const int bh   = blockIdx.y;
    const int q0   = blockIdx.x << 6;
    const float* Qg = g_q + bh * N_ * DH_;
    const float* Kg = g_k + bh * N_ * DH_;
    const float* Vg = g_v + bh * N_ * DH_;

    const int kvr = tid >> 4, kvc = (tid & 15) << 2;
    const int lr  = tid >> 4, lc  = (tid & 15) << 2;

    // Load Q tile (mod-513 remap, *dh^-0.5) and K/V chunk 0.
#pragma unroll
    for (int p = 0; p < 8; ++p) {
        int r  = lr + (p << 3);
        int gn = (q0 + r) % QMOD;
        float4 v = *(const float4*)(Qg + gn * DH_ + lc);
        Qs[r][lc + 0] = to_tf32(v.x * 0.125f);
        Qs[r][lc + 1] = to_tf32(v.y * 0.125f);
        Qs[r][lc + 2] = to_tf32(v.z * 0.125f);
        Qs[r][lc + 3] = to_tf32(v.w * 0.125f);
    }
#pragma unroll
    for (int p = 0; p < 8; ++p) {
        int r = kvr + (p << 3);
        *(float4*)&Ks[r][kvc] = cvt4(*(const float4*)(Kg + r * DH_ + kvc));
        *(float4*)&Vs[r][kvc] = cvt4(*(const float4*)(Vg + r * DH_ + kvc));
    }
    __syncthreads();

    const int wq = warp << 4;

    // Hoist Q fragments: loop-invariant across all kt chunks.
    unsigned qf[8][4];
#pragma unroll
    for (int ks = 0; ks < 8; ++ks) {
        const int kk = ks << 3;
        int r = wq + gid;
        qf[ks][0] = __float_as_uint(Qs[r][kk + tig]);
        qf[ks][1] = __float_as_uint(Qs[r + 8][kk + tig]);
        qf[ks][2] = __float_as_uint(Qs[r][kk + tig + 4]);
        qf[ks][3] = __float_as_uint(Qs[r + 8][kk + tig + 4]);
    }

    float4 o[8];
#pragma unroll
    for (int nt = 0; nt < 8; ++nt) o[nt] = make_float4(0.f, 0.f, 0.f, 0.f);
    float m0 = -1e30f, m1 = -1e30f, l0 = 0.f, l1 = 0.f;

    for (int kt = 0; kt < N_; kt += 64) {
        // ---- S = Q * K^T  (16 rows x 64 cols per warp) ----
        float4 s[8];
#pragma unroll
        for (int nt = 0; nt < 8; ++nt) s[nt] = make_float4(0.f, 0.f, 0.f, 0.f);
#pragma unroll
        for (int ks = 0; ks < 8; ++ks) {
            const int kk = ks << 3;
            unsigned b[8][2];
#pragma unroll
            for (int nt = 0; nt < 8; ++nt) {
                int c = (nt << 3) + gid;           // token index
                b[nt][0] = __float_as_uint(Ks[c][kk + tig]);
                b[nt][1] = __float_as_uint(Ks[c][kk + tig + 4]);
            }
#pragma unroll
            for (int nt = 0; nt < 8; ++nt) mma8(s[nt], qf[ks], b[nt], s[nt]);
        }

        // ---- online softmax (r0 = wq+gid -> .x/.y, r1 = +8 -> .z/.w) ----
        float mx0 = -1e30f, mx1 = -1e30f;
#pragma unroll
        for (int nt = 0; nt < 8; ++nt) {
            mx0 = fmaxf(mx0, fmaxf(s[nt].x, s[nt].y));
            mx1 = fmaxf(mx1, fmaxf(s[nt].z, s[nt].w));
        }
        mx0 = fmaxf(mx0, __shfl_xor_sync(0xffffffffu, mx0, 1));
        mx0 = fmaxf(mx0, __shfl_xor_sync(0xffffffffu, mx0, 2));
        mx1 = fmaxf(mx1, __shfl_xor_sync(0xffffffffu, mx1, 1));
        mx1 = fmaxf(mx1, __shfl_xor_sync(0xffffffffu, mx1, 2));
        float mn0 = fmaxf(m0, mx0), mn1 = fmaxf(m1, mx1);
        float al0 = __expf(m0 - mn0), al1 = __expf(m1 - mn1);
        m0 = mn0; m1 = mn1;
        float ps0 = 0.f, ps1 = 0.f;
#pragma unroll
        for (int nt = 0; nt < 8; ++nt) {
            float px = __expf(s[nt].x - mn0), py = __expf(s[nt].y - mn0);
            float pz = __expf(s[nt].z - mn1), pw = __expf(s[nt].w - mn1);
            ps0 += px + py; ps1 += pz + pw;
            int c = (nt << 3) + (tig << 1);
            *(float2*)&Ps[wq + gid][c]     = make_float2(to_tf32(px), to_tf32(py));
            *(float2*)&Ps[wq + gid + 8][c] = make_float2(to_tf32(pz), to_tf32(pw));
        }
        ps0 += __shfl_xor_sync(0xffffffffu, ps0, 1);
        ps0 += __shfl_xor_sync(0xffffffffu, ps0, 2);
        ps1 += __shfl_xor_sync(0xffffffffu, ps1, 1);
        ps1 += __shfl_xor_sync(0xffffffffu, ps1, 2);
        l0 = l0 * al0 + ps0;
        l1 = l1 * al1 + ps1;
#pragma unroll
        for (int nt = 0; nt < 8; ++nt) {
            o[nt].x *= al0; o[nt].y *= al0;
            o[nt].z *= al1; o[nt].w *= al1;
        }
        __syncwarp();   // Ps rows are warp-private

        // ---- O += P * V  (16 rows x 64 d per warp, k = 64 tokens) ----
#pragma unroll
        for (int ks = 0; ks < 8; ++ks) {
            const int kk = ks << 3;
            unsigned a[4], b[8][2];
            int r = wq + gid;
            a[0] = __float_as_uint(Ps[r][kk + tig]);
            a[1] = __float_as_uint(Ps[r + 8][kk + tig]);
            a[2] = __float_as_uint(Ps[r][kk + tig + 4]);
            a[3] = __float_as_uint(Ps[r + 8][kk + tig + 4]);
#pragma unroll
            for (int nt = 0; nt < 8; ++nt) {
                int c = (nt << 3) + gid;           // d index
                b[nt][0] = __float_as_uint(Vs[kk + tig][c]);
                b[nt][1] = __float_as_uint(Vs[kk + tig + 4][c]);
            }
#pragma unroll
            for (int nt = 0; nt < 8; ++nt) mma8(o[nt], a, b[nt], o[nt]);
        }

        if (kt + 64 < N_) {
            __syncthreads();     // all warps done reading Ks/Vs
#pragma unroll
            for (int p = 0; p < 8; ++p) {
                int r = kvr + (p << 3);
                *(float4*)&Ks[r][kvc]
                    = cvt4(*(const float4*)(Kg + (kt + 64 + r) * DH_ + kvc));
                *(float4*)&Vs[r][kvc]
                    = cvt4(*(const float4*)(Vg + (kt + 64 + r) * DH_ + kvc));
            }
            __syncthreads();
        }
    }

    // ---- final normalize + store ----
    float inv0 = 1.f / l0, inv1 = 1.f / l1;
    const int bb = bh >> 3, h = bh & 7;
    int nr0 = q0 + wq + gid;
    float* base0 = g_cat + ((bb * N_ + nr0) * H_ + h) * 128;
    float* base1 = g_cat + ((bb * N_ + nr0 + 8) * H_ + h) * 128;
#pragma unroll
    for (int nt = 0; nt < 8; ++nt) {
        int d = (nt << 3) + (tig << 1);
        *(float2*)(base0 + d) = make_float2(o[nt].x * inv0, o[nt].y * inv0);
        *(float2*)(base1 + d) = make_float2(o[nt].z * inv1, o[nt].w * inv1);
    }
}

// ---------------------------------------------------------------------------
// Kernel 3: out2 = attn2 @ t as segmented geometric IIR scans (halo 64;
// r^64 ~ 6e-11 so segment error ~1e-10).
// ---------------------------------------------------------------------------
#define SEG_  256
#define HALO_ 64
__global__ __launch_bounds__(128) void k_scan()
{
    __shared__ float sinv[N_];
    const int tid = threadIdx.x;
    const float inv_e = 0.36787944117144233f;   // 1/e
    const float r     = 0.69220062755534635f;   // exp(-1/e)
    const float cgeo  = 1.0f / (1.0f - r);
    for (int i = tid; i < N_; i += 128) {
        float s = 1.0f + (r - __expf(-(float)(i + 1) * inv_e)) * cgeo
                       + (r - __expf(-(float)(N_ - i) * inv_e)) * cgeo;
        sinv[i] = 1.0f / s;
    }
    __syncthreads();

    const int gidx = (blockIdx.x << 7) + tid;   // 0..8191
    const int d    = gidx & 63;
    const int rest = gidx >> 6;                 // 0..127
    const int seg  = rest & 7;
    const int bh   = rest >> 3;                 // 0..15
    const int b    = bh >> 3, h = bh & 7;
    const float* tp = g_t + bh * N_ * DH_ + d;
    float* cp = g_cat + (b * N_ * H_) * 128 + h * 128 + 64 + d;
    const int s0 = seg * SEG_;
    const int e0 = s0 + SEG_;

    float f = 0.f;
    {
        int w0 = (seg == 0) ? 0 : s0 - HALO_;
        for (int i = w0; i < s0; ++i)
            f = fmaf(r, f, tp[i * DH_] * sinv[i]);
    }
    for (int base = s0; base < e0; base += 16) {
        float u[16];
#pragma unroll
        for (int q = 0; q < 16; ++q)
            u[q] = tp[(base + q) * DH_] * sinv[base + q];
#pragma unroll
        for (int q = 0; q < 16; ++q) {
            f = fmaf(r, f, u[q]);
            cp[(base + q) * 1024] = f;
        }
    }

    float g = 0.f;
    {
        int w1 = (e0 + HALO_ > N_) ? N_ : e0 + HALO_;
        for (int i = w1 - 1; i >= e0; --i)
            g = r * (tp[i * DH_] * sinv[i] + g);
    }
    for (int base = e0 - 16; base >= s0; base -= 16) {
        float u[16];
#pragma unroll
        for (int q = 0; q < 16; ++q)
            u[q] = tp[(base + q) * DH_] * sinv[base + q];
#pragma unroll
        for (int q = 15; q >= 0; --q) {
            cp[(base + q) * 1024] += g;
            g = r * (u[q] + g);
        }
    }
}

// ---------------------------------------------------------------------------
// Kernel 4: out = g_cat[4096,1024] @ W_out[1024,512] + b_out (tf32 MMA,
// 128x64 tile, double-buffered, 2 CTAs/SM).
// ---------------------------------------------------------------------------
__global__ __launch_bounds__(256, 2) void k_gemm_out(const float* __restrict__ W,
                                                     const float* __restrict__ bias,
                                                     float* __restrict__ out)
{
    __shared__ float As[2][128][36];
    __shared__ float Bs[2][32][72];
    const int tid  = threadIdx.x;
    const int lane = tid & 31, warp = tid >> 5;
    const int gid  = lane >> 2, tig = lane & 3;
    const int row0 = blockIdx.y << 7, col0 = blockIdx.x << 6;
    const int wm = (warp & 3) << 5;
    const int wn = (warp >> 2) << 5;

    float4 acc[2][4];
#pragma unroll
    for (int i = 0; i < 2; ++i)
#pragma unroll
        for (int j = 0; j < 4; ++j) acc[i][j] = make_float4(0.f, 0.f, 0.f, 0.f);

    const int ar_ = tid >> 3, ac_ = (tid & 7) << 2;
    const int br_ = tid >> 4, bc_ = (tid & 15) << 2;

    float4 ra[4], rb[2];
#pragma unroll
    for (int p = 0; p < 4; ++p)
        ra[p] = *(const float4*)(g_cat + (row0 + ar_ + (p << 5)) * 1024 + ac_);
#pragma unroll
    for (int p = 0; p < 2; ++p)
        rb[p] = *(const float4*)(W + (br_ + (p << 4)) * 512 + col0 + bc_);
#pragma unroll
    for (int p = 0; p < 4; ++p)
        *(float4*)&As[0][ar_ + (p << 5)][ac_] = cvt4(ra[p]);
#pragma unroll
    for (int p = 0; p < 2; ++p)
        *(float4*)&Bs[0][br_ + (p << 4)][bc_] = cvt4(rb[p]);
    __syncthreads();

    int buf = 0;
    for (int k0 = 0; k0 < 1024; k0 += 32) {
        const bool nxt = (k0 + 32) < 1024;
        if (nxt) {
#pragma unroll
            for (int p = 0; p < 4; ++p)
                ra[p] = *(const float4*)(g_cat + (row0 + ar_ + (p << 5)) * 1024
                                         + k0 + 32 + ac_);
#pragma unroll
            for (int p = 0; p < 2; ++p)
                rb[p] = *(const float4*)(W + (k0 + 32 + br_ + (p << 4)) * 512
                                         + col0 + bc_);
        }
        float (*Ac)[36] = As[buf];
        float (*Bc)[72] = Bs[buf];
#pragma unroll
        for (int ks = 0; ks < 4; ++ks) {
            const int kk = ks << 3;
            unsigned a[2][4], b[4][2];
#pragma unroll
            for (int mt = 0; mt < 2; ++mt) {
                int r = wm + (mt << 4) + gid;
                a[mt][0] = __float_as_uint(Ac[r][kk + tig]);
                a[mt][1] = __float_as_uint(Ac[r + 8][kk + tig]);
                a[mt][2] = __float_as_uint(Ac[r][kk + tig + 4]);
                a[mt][3] = __float_as_uint(Ac[r + 8][kk + tig + 4]);
            }
#pragma unroll
            for (int nt = 0; nt < 4; ++nt) {
                int c = wn + (nt << 3) + gid;
                b[nt][0] = __float_as_uint(Bc[kk + tig][c]);
                b[nt][1] = __float_as_uint(Bc[kk + tig + 4][c]);
            }
#pragma unroll
            for (int mt = 0; mt < 2; ++mt)
#pragma unroll
                for (int nt = 0; nt < 4; ++nt)
                    mma8(acc[mt][nt], a[mt], b[nt], acc[mt][nt]);
        }
        if (nxt) {
            float (*An)[36] = As[buf ^ 1];
            float (*Bn)[72] = Bs[buf ^ 1];
#pragma unroll
            for (int p = 0; p < 4; ++p)
                *(float4*)&An[ar_ + (p << 5)][ac_] = cvt4(ra[p]);
#pragma unroll
            for (int p = 0; p < 2; ++p)
                *(float4*)&Bn[br_ + (p << 4)][bc_] = cvt4(rb[p]);
        }
        __syncthreads();
        buf ^= 1;
    }

#pragma unroll
    for (int mt = 0; mt < 2; ++mt) {
        int gr0 = row0 + wm + (mt << 4) + gid;
        int gr1 = gr0 + 8;
#pragma unroll
        for (int nt = 0; nt < 4; ++nt) {
            int gc = col0 + wn + (nt << 3) + (tig << 1);
            float2 bv = *(const float2*)(bias + gc);
            *(float2*)(out + gr0 * 512 + gc)
                = make_float2(acc[mt][nt].x + bv.x, acc[mt][nt].y + bv.y);
            *(float2*)(out + gr1 * 512 + gc)
                = make_float2(acc[mt][nt].z + bv.x, acc[mt][nt].w + bv.y);
        }
    }
}

// ---------------------------------------------------------------------------
extern "C" void kernel_launch(void* const* d_in, const int* in_sizes, int n_in,
                              void* d_out, int out_size)
{
    (void)in_sizes; (void)n_in; (void)out_size;
    const float* x     = (const float*)d_in[0];
    const float* W_qkv = (const float*)d_in[1];
    const float* W_out = (const float*)d_in[2];
    const float* b_out = (const float*)d_in[3];
    float* out = (float*)d_out;

    k_gemm_qkv<<<dim3(32, 32), 256>>>(x, W_qkv);   // qkvt projection (tf32)
    k_attn    <<<dim3(32, 16), 128>>>();           // attn1 flash (chunk-64)
    k_scan    <<<64, 128>>>();                     // attn2 (segmented IIR)
    k_gemm_out<<<dim3(8, 32), 256>>>(W_out, b_out, out);
}

// round 15
// speedup vs baseline: 1.1521x; 1.1521x over previous
#include <cuda_runtime.h>

#define B_   2
#define N_   2048
#define H_   8
#define DH_  64
#define BH_  16
#define QMOD 513

// Scratch (device globals; no runtime allocation allowed).
__device__ float g_q[BH_ * N_ * DH_];
__device__ float g_k[BH_ * N_ * DH_];
__device__ float g_v[BH_ * N_ * DH_];
__device__ float g_t[BH_ * N_ * DH_];
__device__ float g_cat[B_ * N_ * H_ * 2 * DH_];   // [b][n][h][128]

// ---------------------------------------------------------------------------
// TF32 helpers
// ---------------------------------------------------------------------------
__device__ __forceinline__ float to_tf32(float x) {
    float r;
    asm("cvt.rna.tf32.f32 %0, %1;" : "=f"(r) : "f"(x));
    return r;
}
__device__ __forceinline__ float4 cvt4(float4 v) {
    v.x = to_tf32(v.x); v.y = to_tf32(v.y);
    v.z = to_tf32(v.z); v.w = to_tf32(v.w);
    return v;
}

// D = A(16x8,row) * B(8x8,col) + C, tf32 inputs, f32 accumulate.
__device__ __forceinline__ void mma8(float4& d, const unsigned* a,
                                     const unsigned* b, const float4& c) {
    asm volatile(
        "mma.sync.aligned.m16n8k8.row.col.f32.tf32.tf32.f32 "
        "{%0,%1,%2,%3}, {%4,%5,%6,%7}, {%8,%9}, {%10,%11,%12,%13};\n"
        : "=f"(d.x), "=f"(d.y), "=f"(d.z), "=f"(d.w)
        : "r"(a[0]), "r"(a[1]), "r"(a[2]), "r"(a[3]),
          "r"(b[0]), "r"(b[1]),
          "f"(c.x), "f"(c.y), "f"(c.z), "f"(c.w));
}

// ---------------------------------------------------------------------------
// Kernel 1: qkvt = X[4096,512] @ W_qkv[512,2048]  (tf32 MMA, 128x128 tile,
// double-buffered SMEM + register-staged prefetch).  [305us-proven config]
// ---------------------------------------------------------------------------
__global__ __launch_bounds__(256) void k_gemm_qkv(const float* __restrict__ X,
                                                  const float* __restrict__ W)
{
    __shared__ float As[2][128][36];
    __shared__ float Bs[2][32][136];
    const int tid  = threadIdx.x;
    const int lane = tid & 31, warp = tid >> 5;
    const int gid  = lane >> 2, tig = lane & 3;
    const int row0 = blockIdx.y << 7, col0 = blockIdx.x << 7;
    const int wm = (warp & 3) << 5;
    const int wn = (warp >> 2) << 6;

    float4 acc[2][8];
#pragma unroll
    for (int i = 0; i < 2; ++i)
#pragma unroll
        for (int j = 0; j < 8; ++j) acc[i][j] = make_float4(0.f, 0.f, 0.f, 0.f);

    const int ar_ = tid >> 3, ac_ = (tid & 7) << 2;   // A: 32 rows/pass
    const int br_ = tid >> 5, bc_ = (tid & 31) << 2;  // B: 8 rows/pass

    float4 ra[4], rb[4];
#pragma unroll
    for (int p = 0; p < 4; ++p)
        ra[p] = *(const float4*)(X + (row0 + ar_ + (p << 5)) * 512 + ac_);
#pragma unroll
    for (int p = 0; p < 4; ++p)
        rb[p] = *(const float4*)(W + (br_ + (p << 3)) * 2048 + col0 + bc_);
#pragma unroll
    for (int p = 0; p < 4; ++p)
        *(float4*)&As[0][ar_ + (p << 5)][ac_] = cvt4(ra[p]);
#pragma unroll
    for (int p = 0; p < 4; ++p)
        *(float4*)&Bs[0][br_ + (p << 3)][bc_] = cvt4(rb[p]);
    __syncthreads();

    int buf = 0;
    for (int k0 = 0; k0 < 512; k0 += 32) {
        const bool nxt = (k0 + 32) < 512;
        if (nxt) {
#pragma unroll
            for (int p = 0; p < 4; ++p)
                ra[p] = *(const float4*)(X + (row0 + ar_ + (p << 5)) * 512
                                         + k0 + 32 + ac_);
#pragma unroll
            for (int p = 0; p < 4; ++p)
                rb[p] = *(const float4*)(W + (k0 + 32 + br_ + (p << 3)) * 2048
                                         + col0 + bc_);
        }
        float (*Ac)[36]  = As[buf];
        float (*Bc)[136] = Bs[buf];
#pragma unroll
        for (int ks = 0; ks < 4; ++ks) {
            const int kk = ks << 3;
            unsigned a[2][4], b[8][2];
#pragma unroll
            for (int mt = 0; mt < 2; ++mt) {
                int r = wm + (mt << 4) + gid;
                a[mt][0] = __float_as_uint(Ac[r][kk + tig]);
                a[mt][1] = __float_as_uint(Ac[r + 8][kk + tig]);
                a[mt][2] = __float_as_uint(Ac[r][kk + tig + 4]);
                a[mt][3] = __float_as_uint(Ac[r + 8][kk + tig + 4]);
            }
#pragma unroll
            for (int nt = 0; nt < 8; ++nt) {
                int c = wn + (nt << 3) + gid;
                b[nt][0] = __float_as_uint(Bc[kk + tig][c]);
                b[nt][1] = __float_as_uint(Bc[kk + tig + 4][c]);
            }
#pragma unroll
            for (int mt = 0; mt < 2; ++mt)
#pragma unroll
                for (int nt = 0; nt < 8; ++nt)
                    mma8(acc[mt][nt], a[mt], b[nt], acc[mt][nt]);
        }
        if (nxt) {
            float (*An)[36]  = As[buf ^ 1];
            float (*Bn)[136] = Bs[buf ^ 1];
#pragma unroll
            for (int p = 0; p < 4; ++p)
                *(float4*)&An[ar_ + (p << 5)][ac_] = cvt4(ra[p]);
#pragma unroll
            for (int p = 0; p < 4; ++p)
                *(float4*)&Bn[br_ + (p << 3)][bc_] = cvt4(rb[p]);
        }
        __syncthreads();
        buf ^= 1;
    }

    // Scatter epilogue: section (q/k/v/t), head, d from the global column.
#pragma unroll
    for (int mt = 0; mt < 2; ++mt) {
        int gr0 = row0 + wm + (mt << 4) + gid;
        int gr1 = gr0 + 8;
        int b0i = gr0 >> 11, n0i = gr0 & (N_ - 1);
        int b1i = gr1 >> 11, n1i = gr1 & (N_ - 1);
#pragma unroll
        for (int nt = 0; nt < 8; ++nt) {
            int gc  = col0 + wn + (nt << 3) + (tig << 1);
            int sec = gc >> 9, h = (gc >> 6) & 7, d = gc & 63;
            float* dst = (sec == 0) ? g_q : (sec == 1) ? g_k
                       : (sec == 2) ? g_v : g_t;
            *(float2*)(dst + (((b0i << 3) | h) * N_ + n0i) * DH_ + d)
                = make_float2(acc[mt][nt].x, acc[mt][nt].y);
            *(float2*)(dst + (((b1i << 3) | h) * N_ + n1i) * DH_ + d)
                = make_float2(acc[mt][nt].z, acc[mt][nt].w);
        }
    }
}

// ---------------------------------------------------------------------------
// Kernel 2: flash attention (attn1), tf32 MMA. Q-tile 128, 4 warps, each
// warp owns 32 q-rows (mt=2): K/V fragment bytes amortize over 2x MMAs
// (crossbar-bound fix). K-chunk 32, single-buffered, 3 CTAs/SM.
// ---------------------------------------------------------------------------
__global__ __launch_bounds__(128, 3) void k_attn()
{
    __shared__ float Qs[128][68];   // A operand [q][d]
    __shared__ float Ks[32][68];    // B operand for S: [token][d]
    __shared__ float Vs[32][72];    // B operand for PV: [token][d]
    __shared__ float Ps[128][36];   // A operand for PV: [q][token]

    const int tid  = threadIdx.x;
    const int lane = tid & 31, warp = tid >> 5;
    const int gid  = lane >> 2, tig = lane & 3;
    const int bh   = blockIdx.y;
    const int q0   = blockIdx.x << 7;
    const float* Qg = g_q + bh * N_ * DH_;
    const float* Kg = g_k + bh * N_ * DH_;
    const float* Vg = g_v + bh * N_ * DH_;

    const int lr  = tid >> 4, lc  = (tid & 15) << 2;
    const int kvr = tid >> 4, kvc = (tid & 15) << 2;

    // Load Q tile (mod-513 remap, *dh^-0.5): 128 rows.
#pragma unroll
    for (int p = 0; p < 16; ++p) {
        int r  = lr + (p << 3);
        int gn = (q0 + r) % QMOD;
        float4 v = *(const float4*)(Qg + gn * DH_ + lc);
        Qs[r][lc + 0] = to_tf32(v.x * 0.125f);
        Qs[r][lc + 1] = to_tf32(v.y * 0.125f);
        Qs[r][lc + 2] = to_tf32(v.z * 0.125f);
        Qs[r][lc + 3] = to_tf32(v.w * 0.125f);
    }
    // K/V chunk 0.
#pragma unroll
    for (int p = 0; p < 4; ++p) {
        int r = kvr + (p << 3);
        *(float4*)&Ks[r][kvc] = cvt4(*(const float4*)(Kg + r * DH_ + kvc));
        *(float4*)&Vs[r][kvc] = cvt4(*(const float4*)(Vg + r * DH_ + kvc));
    }
    __syncthreads();

    const int wq = warp << 5;      // 32 q-rows per warp

    float4 o[2][8];
#pragma unroll
    for (int mt = 0; mt < 2; ++mt)
#pragma unroll
        for (int nt = 0; nt < 8; ++nt) o[mt][nt] = make_float4(0.f, 0.f, 0.f, 0.f);
    float m[2][2] = {{-1e30f, -1e30f}, {-1e30f, -1e30f}};
    float l[2][2] = {{0.f, 0.f}, {0.f, 0.f}};

    for (int kt = 0; kt < N_; kt += 32) {
        // ---- S = Q * K^T  (32 rows x 32 cols per warp) ----
        float4 s[2][4];
#pragma unroll
        for (int mt = 0; mt < 2; ++mt)
#pragma unroll
            for (int nt = 0; nt < 4; ++nt) s[mt][nt] = make_float4(0.f, 0.f, 0.f, 0.f);
#pragma unroll
        for (int ks = 0; ks < 8; ++ks) {
            const int kk = ks << 3;
            unsigned a[2][4], b[4][2];
#pragma unroll
            for (int mt = 0; mt < 2; ++mt) {
                int r = wq + (mt << 4) + gid;
                a[mt][0] = __float_as_uint(Qs[r][kk + tig]);
                a[mt][1] = __float_as_uint(Qs[r + 8][kk + tig]);
                a[mt][2] = __float_as_uint(Qs[r][kk + tig + 4]);
                a[mt][3] = __float_as_uint(Qs[r + 8][kk + tig + 4]);
            }
#pragma unroll
            for (int nt = 0; nt < 4; ++nt) {
                int c = (nt << 3) + gid;           // token index
                b[nt][0] = __float_as_uint(Ks[c][kk + tig]);
                b[nt][1] = __float_as_uint(Ks[c][kk + tig + 4]);
            }
#pragma unroll
            for (int mt = 0; mt < 2; ++mt)
#pragma unroll
                for (int nt = 0; nt < 4; ++nt)
                    mma8(s[mt][nt], a[mt], b[nt], s[mt][nt]);
        }

        // ---- online softmax per 16-row tile ----
        float alpha[2][2];
#pragma unroll
        for (int mt = 0; mt < 2; ++mt) {
            float mx0 = -1e30f, mx1 = -1e30f;
#pragma unroll
            for (int nt = 0; nt < 4; ++nt) {
                mx0 = fmaxf(mx0, fmaxf(s[mt][nt].x, s[mt][nt].y));
                mx1 = fmaxf(mx1, fmaxf(s[mt][nt].z, s[mt][nt].w));
            }
            mx0 = fmaxf(mx0, __shfl_xor_sync(0xffffffffu, mx0, 1));
            mx0 = fmaxf(mx0, __shfl_xor_sync(0xffffffffu, mx0, 2));
            mx1 = fmaxf(mx1, __shfl_xor_sync(0xffffffffu, mx1, 1));
            mx1 = fmaxf(mx1, __shfl_xor_sync(0xffffffffu, mx1, 2));
            float mn0 = fmaxf(m[mt][0], mx0), mn1 = fmaxf(m[mt][1], mx1);
            alpha[mt][0] = __expf(m[mt][0] - mn0);
            alpha[mt][1] = __expf(m[mt][1] - mn1);
            m[mt][0] = mn0; m[mt][1] = mn1;
            float ps0 = 0.f, ps1 = 0.f;
            int r = wq + (mt << 4) + gid;
#pragma unroll
            for (int nt = 0; nt < 4; ++nt) {
                float px = __expf(s[mt][nt].x - mn0), py = __expf(s[mt][nt].y - mn0);
                float pz = __expf(s[mt][nt].z - mn1), pw = __expf(s[mt][nt].w - mn1);
                ps0 += px + py; ps1 += pz + pw;
                int c = (nt << 3) + (tig << 1);
                *(float2*)&Ps[r][c]     = make_float2(to_tf32(px), to_tf32(py));
                *(float2*)&Ps[r + 8][c] = make_float2(to_tf32(pz), to_tf32(pw));
            }
            ps0 += __shfl_xor_sync(0xffffffffu, ps0, 1);
            ps0 += __shfl_xor_sync(0xffffffffu, ps0, 2);
            ps1 += __shfl_xor_sync(0xffffffffu, ps1, 1);
            ps1 += __shfl_xor_sync(0xffffffffu, ps1, 2);
            l[mt][0] = l[mt][0] * alpha[mt][0] + ps0;
            l[mt][1] = l[mt][1] * alpha[mt][1] + ps1;
        }
#pragma unroll
        for (int mt = 0; mt < 2; ++mt)
#pragma unroll
            for (int nt = 0; nt < 8; ++nt) {
                o[mt][nt].x *= alpha[mt][0]; o[mt][nt].y *= alpha[mt][0];
                o[mt][nt].z *= alpha[mt][1]; o[mt][nt].w *= alpha[mt][1];
            }
        __syncwarp();   // Ps rows are warp-private

        // ---- O += P * V  (32 rows x 64 d per warp) ----
#pragma unroll
        for (int ks = 0; ks < 4; ++ks) {
            const int kk = ks << 3;
            unsigned a[2][4], b[8][2];
#pragma unroll
            for (int mt = 0; mt < 2; ++mt) {
                int r = wq + (mt << 4) + gid;
                a[mt][0] = __float_as_uint(Ps[r][kk + tig]);
                a[mt][1] = __float_as_uint(Ps[r + 8][kk + tig]);
                a[mt][2] = __float_as_uint(Ps[r][kk + tig + 4]);
                a[mt][3] = __float_as_uint(Ps[r + 8][kk + tig + 4]);
            }
#pragma unroll
            for (int nt = 0; nt < 8; ++nt) {
                int c = (nt << 3) + gid;           // d index
                b[nt][0] = __float_as_uint(Vs[kk + tig][c]);
                b[nt][1] = __float_as_uint(Vs[kk + tig + 4][c]);
            }
#pragma unroll
            for (int mt = 0; mt < 2; ++mt)
#pragma unroll
                for (int nt = 0; nt < 8; ++nt)
                    mma8(o[mt][nt], a[mt], b[nt], o[mt][nt]);
        }

        if (kt + 32 < N_) {
            __syncthreads();     // all warps done reading Ks/Vs
#pragma unroll
            for (int p = 0; p < 4; ++p) {
                int r = kvr + (p << 3);
                *(float4*)&Ks[r][kvc]
                    = cvt4(*(const float4*)(Kg + (kt + 32 + r) * DH_ + kvc));
                *(float4*)&Vs[r][kvc]
                    = cvt4(*(const float4*)(Vg + (kt + 32 + r) * DH_ + kvc));
            }
            __syncthreads();
        }
    }

    // ---- final normalize + store ----
    const int bb = bh >> 3, h = bh & 7;
#pragma unroll
    for (int mt = 0; mt < 2; ++mt) {
        float inv0 = 1.f / l[mt][0], inv1 = 1.f / l[mt][1];
        int nr0 = q0 + wq + (mt << 4) + gid;
        float* base0 = g_cat + ((bb * N_ + nr0) * H_ + h) * 128;
        float* base1 = g_cat + ((bb * N_ + nr0 + 8) * H_ + h) * 128;
#pragma unroll
        for (int nt = 0; nt < 8; ++nt) {
            int d = (nt << 3) + (tig << 1);
            *(float2*)(base0 + d)
                = make_float2(o[mt][nt].x * inv0, o[mt][nt].y * inv0);
            *(float2*)(base1 + d)
                = make_float2(o[mt][nt].z * inv1, o[mt][nt].w * inv1);
        }
    }
}

// ---------------------------------------------------------------------------
// Kernel 3: out2 = attn2 @ t as segmented geometric IIR scans (halo 64;
// r^64 ~ 6e-11 so segment error ~1e-10).
// ---------------------------------------------------------------------------
#define SEG_  256
#define HALO_ 64
__global__ __launch_bounds__(128) void k_scan()
{
    __shared__ float sinv[N_];
    const int tid = threadIdx.x;
    const float inv_e = 0.36787944117144233f;   // 1/e
    const float r     = 0.69220062755534635f;   // exp(-1/e)
    const float cgeo  = 1.0f / (1.0f - r);
    for (int i = tid; i < N_; i += 128) {
        float s = 1.0f + (r - __expf(-(float)(i + 1) * inv_e)) * cgeo
                       + (r - __expf(-(float)(N_ - i) * inv_e)) * cgeo;
        sinv[i] = 1.0f / s;
    }
    __syncthreads();

    const int gidx = (blockIdx.x << 7) + tid;   // 0..8191
    const int d    = gidx & 63;
    const int rest = gidx >> 6;                 // 0..127
    const int seg  = rest & 7;
    const int bh   = rest >> 3;                 // 0..15
    const int b    = bh >> 3, h = bh & 7;
    const float* tp = g_t + bh * N_ * DH_ + d;
    float* cp = g_cat + (b * N_ * H_) * 128 + h * 128 + 64 + d;
    const int s0 = seg * SEG_;
    const int e0 = s0 + SEG_;

    float f = 0.f;
    {
        int w0 = (seg == 0) ? 0 : s0 - HALO_;
        for (int i = w0; i < s0; ++i)
            f = fmaf(r, f, tp[i * DH_] * sinv[i]);
    }
    for (int base = s0; base < e0; base += 16) {
        float u[16];
#pragma unroll
        for (int q = 0; q < 16; ++q)
            u[q] = tp[(base + q) * DH_] * sinv[base + q];
#pragma unroll
        for (int q = 0; q < 16; ++q) {
            f = fmaf(r, f, u[q]);
            cp[(base + q) * 1024] = f;
        }
    }

    float g = 0.f;
    {
        int w1 = (e0 + HALO_ > N_) ? N_ : e0 + HALO_;
        for (int i = w1 - 1; i >= e0; --i)
            g = r * (tp[i * DH_] * sinv[i] + g);
    }
    for (int base = e0 - 16; base >= s0; base -= 16) {
        float u[16];
#pragma unroll
        for (int q = 0; q < 16; ++q)
            u[q] = tp[(base + q) * DH_] * sinv[base + q];
#pragma unroll
        for (int q = 15; q >= 0; --q) {
            cp[(base + q) * 1024] += g;
            g = r * (u[q] + g);
        }
    }
}

// ---------------------------------------------------------------------------
// Kernel 4: out = g_cat[4096,1024] @ W_out[1024,512] + b_out (tf32 MMA,
// 128x128 tile, double-buffered).  [305us-proven config]
// ---------------------------------------------------------------------------
__global__ __launch_bounds__(256) void k_gemm_out(const float* __restrict__ W,
                                                  const float* __restrict__ bias,
                                                  float* __restrict__ out)
{
    __shared__ float As[2][128][36];
    __shared__ float Bs[2][32][136];
    const int tid  = threadIdx.x;
    const int lane = tid & 31, warp = tid >> 5;
    const int gid  = lane >> 2, tig = lane & 3;
    const int row0 = blockIdx.y << 7, col0 = blockIdx.x << 7;
    const int wm = (warp & 3) << 5;
    const int wn = (warp >> 2) << 6;

    float4 acc[2][8];
#pragma unroll
    for (int i = 0; i < 2; ++i)
#pragma unroll
        for (int j = 0; j < 8; ++j) acc[i][j] = make_float4(0.f, 0.f, 0.f, 0.f);

    const int ar_ = tid >> 3, ac_ = (tid & 7) << 2;
    const int br_ = tid >> 5, bc_ = (tid & 31) << 2;

    float4 ra[4], rb[4];
#pragma unroll
    for (int p = 0; p < 4; ++p)
        ra[p] = *(const float4*)(g_cat + (row0 + ar_ + (p << 5)) * 1024 + ac_);
#pragma unroll
    for (int p = 0; p < 4; ++p)
        rb[p] = *(const float4*)(W + (br_ + (p << 3)) * 512 + col0 + bc_);
#pragma unroll
    for (int p = 0; p < 4; ++p)
        *(float4*)&As[0][ar_ + (p << 5)][ac_] = cvt4(ra[p]);
#pragma unroll
    for (int p = 0; p < 4; ++p)
        *(float4*)&Bs[0][br_ + (p << 3)][bc_] = cvt4(rb[p]);
    __syncthreads();

    int buf = 0;
    for (int k0 = 0; k0 < 1024; k0 += 32) {
        const bool nxt = (k0 + 32) < 1024;
        if (nxt) {
#pragma unroll
            for (int p = 0; p < 4; ++p)
                ra[p] = *(const float4*)(g_cat + (row0 + ar_ + (p << 5)) * 1024
                                         + k0 + 32 + ac_);
#pragma unroll
            for (int p = 0; p < 4; ++p)
                rb[p] = *(const float4*)(W + (k0 + 32 + br_ + (p << 3)) * 512
                                         + col0 + bc_);
        }
        float (*Ac)[36]  = As[buf];
        float (*Bc)[136] = Bs[buf];
#pragma unroll
        for (int ks = 0; ks < 4; ++ks) {
            const int kk = ks << 3;
            unsigned a[2][4], b[8][2];
#pragma unroll
            for (int mt = 0; mt < 2; ++mt) {
                int r = wm + (mt << 4) + gid;
                a[mt][0] = __float_as_uint(Ac[r][kk + tig]);
                a[mt][1] = __float_as_uint(Ac[r + 8][kk + tig]);
                a[mt][2] = __float_as_uint(Ac[r][kk + tig + 4]);
                a[mt][3] = __float_as_uint(Ac[r + 8][kk + tig + 4]);
            }
#pragma unroll
            for (int nt = 0; nt < 8; ++nt) {
                int c = wn + (nt << 3) + gid;
                b[nt][0] = __float_as_uint(Bc[kk + tig][c]);
                b[nt][1] = __float_as_uint(Bc[kk + tig + 4][c]);
            }
#pragma unroll
            for (int mt = 0; mt < 2; ++mt)
#pragma unroll
                for (int nt = 0; nt < 8; ++nt)
                    mma8(acc[mt][nt], a[mt], b[nt], acc[mt][nt]);
        }
        if (nxt) {
            float (*An)[36]  = As[buf ^ 1];
            float (*Bn)[136] = Bs[buf ^ 1];
#pragma unroll
            for (int p = 0; p < 4; ++p)
                *(float4*)&An[ar_ + (p << 5)][ac_] = cvt4(ra[p]);
#pragma unroll
            for (int p = 0; p < 4; ++p)
                *(float4*)&Bn[br_ + (p << 3)][bc_] = cvt4(rb[p]);
        }
        __syncthreads();
        buf ^= 1;
    }

#pragma unroll
    for (int mt = 0; mt < 2; ++mt) {
        int gr0 = row0 + wm + (mt << 4) + gid;
        int gr1 = gr0 + 8;
#pragma unroll
        for (int nt = 0; nt < 8; ++nt) {
            int gc = col0 + wn + (nt << 3) + (tig << 1);
            float2 bv = *(const float2*)(bias + gc);
            *(float2*)(out + gr0 * 512 + gc)
                = make_float2(acc[mt][nt].x + bv.x, acc[mt][nt].y + bv.y);
            *(float2*)(out + gr1 * 512 + gc)
                = make_float2(acc[mt][nt].z + bv.x, acc[mt][nt].w + bv.y);
        }
    }
}

// ---------------------------------------------------------------------------
extern "C" void kernel_launch(void* const* d_in, const int* in_sizes, int n_in,
                              void* d_out, int out_size)
{
    (void)in_sizes; (void)n_in; (void)out_size;
    const float* x     = (const float*)d_in[0];
    const float* W_qkv = (const float*)d_in[1];
    const float* W_out = (const float*)d_in[2];
    const float* b_out = (const float*)d_in[3];
    float* out = (float*)d_out;

    k_gemm_qkv<<<dim3(16, 32), 256>>>(x, W_qkv);   // qkvt projection (tf32)
    k_attn    <<<dim3(16, 16), 128>>>();           // attn1 flash (mt=2, q128)
    k_scan    <<<64, 128>>>();                     // attn2 (segmented IIR)
    k_gemm_out<<<dim3(4, 32), 256>>>(W_out, b_out, out);
}

// round 17
// speedup vs baseline: 1.2395x; 1.0759x over previous
#include <cuda_runtime.h>

#define B_   2
#define N_   2048
#define H_   8
#define DH_  64
#define BH_  16
#define QMOD 513

// Scratch (device globals; no runtime allocation allowed).
__device__ float g_q[BH_ * N_ * DH_];
__device__ float g_k[BH_ * N_ * DH_];
__device__ float g_v[BH_ * N_ * DH_];
__device__ float g_t[BH_ * N_ * DH_];
__device__ float g_cat[B_ * N_ * H_ * 2 * DH_];   // [b][n][h][128]

// ---------------------------------------------------------------------------
// TF32 helpers
// ---------------------------------------------------------------------------
__device__ __forceinline__ float to_tf32(float x) {
    float r;
    asm("cvt.rna.tf32.f32 %0, %1;" : "=f"(r) : "f"(x));
    return r;
}
__device__ __forceinline__ float4 cvt4(float4 v) {
    v.x = to_tf32(v.x); v.y = to_tf32(v.y);
    v.z = to_tf32(v.z); v.w = to_tf32(v.w);
    return v;
}

// D = A(16x8,row) * B(8x8,col) + C, tf32 inputs, f32 accumulate.
__device__ __forceinline__ void mma8(float4& d, const unsigned* a,
                                     const unsigned* b, const float4& c) {
    asm volatile(
        "mma.sync.aligned.m16n8k8.row.col.f32.tf32.tf32.f32 "
        "{%0,%1,%2,%3}, {%4,%5,%6,%7}, {%8,%9}, {%10,%11,%12,%13};\n"
        : "=f"(d.x), "=f"(d.y), "=f"(d.z), "=f"(d.w)
        : "r"(a[0]), "r"(a[1]), "r"(a[2]), "r"(a[3]),
          "r"(b[0]), "r"(b[1]),
          "f"(c.x), "f"(c.y), "f"(c.z), "f"(c.w));
}

// ---------------------------------------------------------------------------
// Kernel 1: qkvt = X[4096,512] @ W_qkv[512,2048]  (tf32 MMA, 128x128 tile,
// double-buffered SMEM + register-staged prefetch).  [proven config]
// ---------------------------------------------------------------------------
__global__ __launch_bounds__(256) void k_gemm_qkv(const float* __restrict__ X,
                                                  const float* __restrict__ W)
{
    __shared__ float As[2][128][36];
    __shared__ float Bs[2][32][136];
    const int tid  = threadIdx.x;
    const int lane = tid & 31, warp = tid >> 5;
    const int gid  = lane >> 2, tig = lane & 3;
    const int row0 = blockIdx.y << 7, col0 = blockIdx.x << 7;
    const int wm = (warp & 3) << 5;
    const int wn = (warp >> 2) << 6;

    float4 acc[2][8];
#pragma unroll
    for (int i = 0; i < 2; ++i)
#pragma unroll
        for (int j = 0; j < 8; ++j) acc[i][j] = make_float4(0.f, 0.f, 0.f, 0.f);

    const int ar_ = tid >> 3, ac_ = (tid & 7) << 2;   // A: 32 rows/pass
    const int br_ = tid >> 5, bc_ = (tid & 31) << 2;  // B: 8 rows/pass

    float4 ra[4], rb[4];
#pragma unroll
    for (int p = 0; p < 4; ++p)
        ra[p] = *(const float4*)(X + (row0 + ar_ + (p << 5)) * 512 + ac_);
#pragma unroll
    for (int p = 0; p < 4; ++p)
        rb[p] = *(const float4*)(W + (br_ + (p << 3)) * 2048 + col0 + bc_);
#pragma unroll
    for (int p = 0; p < 4; ++p)
        *(float4*)&As[0][ar_ + (p << 5)][ac_] = cvt4(ra[p]);
#pragma unroll
    for (int p = 0; p < 4; ++p)
        *(float4*)&Bs[0][br_ + (p << 3)][bc_] = cvt4(rb[p]);
    __syncthreads();

    int buf = 0;
    for (int k0 = 0; k0 < 512; k0 += 32) {
        const bool nxt = (k0 + 32) < 512;
        if (nxt) {
#pragma unroll
            for (int p = 0; p < 4; ++p)
                ra[p] = *(const float4*)(X + (row0 + ar_ + (p << 5)) * 512
                                         + k0 + 32 + ac_);
#pragma unroll
            for (int p = 0; p < 4; ++p)
                rb[p] = *(const float4*)(W + (k0 + 32 + br_ + (p << 3)) * 2048
                                         + col0 + bc_);
        }
        float (*Ac)[36]  = As[buf];
        float (*Bc)[136] = Bs[buf];
#pragma unroll
        for (int ks = 0; ks < 4; ++ks) {
            const int kk = ks << 3;
            unsigned a[2][4], b[8][2];
#pragma unroll
            for (int mt = 0; mt < 2; ++mt) {
                int r = wm + (mt << 4) + gid;
                a[mt][0] = __float_as_uint(Ac[r][kk + tig]);
                a[mt][1] = __float_as_uint(Ac[r + 8][kk + tig]);
                a[mt][2] = __float_as_uint(Ac[r][kk + tig + 4]);
                a[mt][3] = __float_as_uint(Ac[r + 8][kk + tig + 4]);
            }
#pragma unroll
            for (int nt = 0; nt < 8; ++nt) {
                int c = wn + (nt << 3) + gid;
                b[nt][0] = __float_as_uint(Bc[kk + tig][c]);
                b[nt][1] = __float_as_uint(Bc[kk + tig + 4][c]);
            }
#pragma unroll
            for (int mt = 0; mt < 2; ++mt)
#pragma unroll
                for (int nt = 0; nt < 8; ++nt)
                    mma8(acc[mt][nt], a[mt], b[nt], acc[mt][nt]);
        }
        if (nxt) {
            float (*An)[36]  = As[buf ^ 1];
            float (*Bn)[136] = Bs[buf ^ 1];
#pragma unroll
            for (int p = 0; p < 4; ++p)
                *(float4*)&An[ar_ + (p << 5)][ac_] = cvt4(ra[p]);
#pragma unroll
            for (int p = 0; p < 4; ++p)
                *(float4*)&Bn[br_ + (p << 3)][bc_] = cvt4(rb[p]);
        }
        __syncthreads();
        buf ^= 1;
    }

    // Scatter epilogue: section (q/k/v/t), head, d from the global column.
#pragma unroll
    for (int mt = 0; mt < 2; ++mt) {
        int gr0 = row0 + wm + (mt << 4) + gid;
        int gr1 = gr0 + 8;
        int b0i = gr0 >> 11, n0i = gr0 & (N_ - 1);
        int b1i = gr1 >> 11, n1i = gr1 & (N_ - 1);
#pragma unroll
        for (int nt = 0; nt < 8; ++nt) {
            int gc  = col0 + wn + (nt << 3) + (tig << 1);
            int sec = gc >> 9, h = (gc >> 6) & 7, d = gc & 63;
            float* dst = (sec == 0) ? g_q : (sec == 1) ? g_k
                       : (sec == 2) ? g_v : g_t;
            *(float2*)(dst + (((b0i << 3) | h) * N_ + n0i) * DH_ + d)
                = make_float2(acc[mt][nt].x, acc[mt][nt].y);
            *(float2*)(dst + (((b1i << 3) | h) * N_ + n1i) * DH_ + d)
                = make_float2(acc[mt][nt].z, acc[mt][nt].w);
        }
    }
}

// ---------------------------------------------------------------------------
// Kernel 2 (merged): blocks [0,256) = flash attention (attn1, tf32 MMA,
// q-tile 128, mt=2, K-chunk 32, register-staged K/V prefetch);
// blocks [256,320) = attn2 geometric IIR scans (run concurrently, hidden
// inside the attention wave; 320 blocks <= 444 resident slots @3 CTA/SM).
// ---------------------------------------------------------------------------
#define SEG_  256
#define HALO_ 64
__global__ __launch_bounds__(128, 3) void k_attn_scan()
{
    __shared__ float Qs[128][68];   // A operand [q][d]   (scan: aliased as sinv)
    __shared__ float Ks[32][68];    // B operand for S: [token][d]
    __shared__ float Vs[32][72];    // B operand for PV: [token][d]
    __shared__ float Ps[128][36];   // A operand for PV: [q][token]

    const int tid = threadIdx.x;

    if (blockIdx.x >= 256) {
        // ================= attn2 branch: segmented IIR scan =================
        float* sinv = &Qs[0][0];    // 2048 floats, fits in Qs
        const float inv_e = 0.36787944117144233f;   // 1/e
        const float r     = 0.69220062755534635f;   // exp(-1/e)
        const float cgeo  = 1.0f / (1.0f - r);
        for (int i = tid; i < N_; i += 128) {
            float s = 1.0f + (r - __expf(-(float)(i + 1) * inv_e)) * cgeo
                           + (r - __expf(-(float)(N_ - i) * inv_e)) * cgeo;
            sinv[i] = 1.0f / s;
        }
        __syncthreads();

        const int gidx = ((blockIdx.x - 256) << 7) + tid;   // 0..8191
        const int d    = gidx & 63;
        const int rest = gidx >> 6;                 // 0..127
        const int seg  = rest & 7;
        const int bh   = rest >> 3;                 // 0..15
        const int b    = bh >> 3, h = bh & 7;
        const float* tp = g_t + bh * N_ * DH_ + d;
        float* cp = g_cat + (b * N_ * H_) * 128 + h * 128 + 64 + d;
        const int s0 = seg * SEG_;
        const int e0 = s0 + SEG_;

        float f = 0.f;
        {
            int w0 = (seg == 0) ? 0 : s0 - HALO_;
            for (int i = w0; i < s0; ++i)
                f = fmaf(r, f, tp[i * DH_] * sinv[i]);
        }
        for (int base = s0; base < e0; base += 16) {
            float u[16];
#pragma unroll
            for (int q = 0; q < 16; ++q)
                u[q] = tp[(base + q) * DH_] * sinv[base + q];
#pragma unroll
            for (int q = 0; q < 16; ++q) {
                f = fmaf(r, f, u[q]);
                cp[(base + q) * 1024] = f;
            }
        }

        float g = 0.f;
        {
            int w1 = (e0 + HALO_ > N_) ? N_ : e0 + HALO_;
            for (int i = w1 - 1; i >= e0; --i)
                g = r * (tp[i * DH_] * sinv[i] + g);
        }
        for (int base = e0 - 16; base >= s0; base -= 16) {
            float u[16];
#pragma unroll
            for (int q = 0; q < 16; ++q)
                u[q] = tp[(base + q) * DH_] * sinv[base + q];
#pragma unroll
            for (int q = 15; q >= 0; --q) {
                cp[(base + q) * 1024] += g;
                g = r * (u[q] + g);
            }
        }
        return;
    }

    // ==================== attn1 branch: flash attention =====================
    const int lane = tid & 31, warp = tid >> 5;
    const int gid  = lane >> 2, tig = lane & 3;
    const int bh   = blockIdx.x >> 4;
    const int q0   = (blockIdx.x & 15) << 7;
    const float* Qg = g_q + bh * N_ * DH_;
    const float* Kg = g_k + bh * N_ * DH_;
    const float* Vg = g_v + bh * N_ * DH_;

    const int lr  = tid >> 4, lc  = (tid & 15) << 2;
    const int kvr = tid >> 4, kvc = (tid & 15) << 2;

    // Load Q tile (mod-513 remap, *dh^-0.5): 128 rows.
#pragma unroll
    for (int p = 0; p < 16; ++p) {
        int r  = lr + (p << 3);
        int gn = (q0 + r) % QMOD;
        float4 v = *(const float4*)(Qg + gn * DH_ + lc);
        Qs[r][lc + 0] = to_tf32(v.x * 0.125f);
        Qs[r][lc + 1] = to_tf32(v.y * 0.125f);
        Qs[r][lc + 2] = to_tf32(v.z * 0.125f);
        Qs[r][lc + 3] = to_tf32(v.w * 0.125f);
    }
    // K/V chunk 0.
#pragma unroll
    for (int p = 0; p < 4; ++p) {
        int r = kvr + (p << 3);
        *(float4*)&Ks[r][kvc] = cvt4(*(const float4*)(Kg + r * DH_ + kvc));
        *(float4*)&Vs[r][kvc] = cvt4(*(const float4*)(Vg + r * DH_ + kvc));
    }
    __syncthreads();

    const int wq = warp << 5;      // 32 q-rows per warp

    float4 o[2][8];
#pragma unroll
    for (int mt = 0; mt < 2; ++mt)
#pragma unroll
        for (int nt = 0; nt < 8; ++nt) o[mt][nt] = make_float4(0.f, 0.f, 0.f, 0.f);
    float m[2][2] = {{-1e30f, -1e30f}, {-1e30f, -1e30f}};
    float l[2][2] = {{0.f, 0.f}, {0.f, 0.f}};

    float4 kreg[4], vreg[4];
    for (int kt = 0; kt < N_; kt += 32) {
        const bool nxt = (kt + 32) < N_;
        // Prefetch next K/V chunk into registers NOW: the ~L2-latency LDGs
        // drain while this chunk's S + softmax + PV compute runs.
        if (nxt) {
#pragma unroll
            for (int p = 0; p < 4; ++p) {
                int r = kvr + (p << 3);
                kreg[p] = *(const float4*)(Kg + (kt + 32 + r) * DH_ + kvc);
                vreg[p] = *(const float4*)(Vg + (kt + 32 + r) * DH_ + kvc);
            }
        }

        // ---- S = Q * K^T  (32 rows x 32 cols per warp) ----
        float4 s[2][4];
#pragma unroll
        for (int mt = 0; mt < 2; ++mt)
#pragma unroll
            for (int nt = 0; nt < 4; ++nt) s[mt][nt] = make_float4(0.f, 0.f, 0.f, 0.f);
#pragma unroll
        for (int ks = 0; ks < 8; ++ks) {
            const int kk = ks << 3;
            unsigned a[2][4], b[4][2];
#pragma unroll
            for (int mt = 0; mt < 2; ++mt) {
                int r = wq + (mt << 4) + gid;
                a[mt][0] = __float_as_uint(Qs[r][kk + tig]);
                a[mt][1] = __float_as_uint(Qs[r + 8][kk + tig]);
                a[mt][2] = __float_as_uint(Qs[r][kk + tig + 4]);
                a[mt][3] = __float_as_uint(Qs[r + 8][kk + tig + 4]);
            }
#pragma unroll
            for (int nt = 0; nt < 4; ++nt) {
                int c = (nt << 3) + gid;           // token index
                b[nt][0] = __float_as_uint(Ks[c][kk + tig]);
                b[nt][1] = __float_as_uint(Ks[c][kk + tig + 4]);
            }
#pragma unroll
            for (int mt = 0; mt < 2; ++mt)
#pragma unroll
                for (int nt = 0; nt < 4; ++nt)
                    mma8(s[mt][nt], a[mt], b[nt], s[mt][nt]);
        }

        // ---- online softmax per 16-row tile ----
        float alpha[2][2];
#pragma unroll
        for (int mt = 0; mt < 2; ++mt) {
            float mx0 = -1e30f, mx1 = -1e30f;
#pragma unroll
            for (int nt = 0; nt < 4; ++nt) {
                mx0 = fmaxf(mx0, fmaxf(s[mt][nt].x, s[mt][nt].y));
                mx1 = fmaxf(mx1, fmaxf(s[mt][nt].z, s[mt][nt].w));
            }
            mx0 = fmaxf(mx0, __shfl_xor_sync(0xffffffffu, mx0, 1));
            mx0 = fmaxf(mx0, __shfl_xor_sync(0xffffffffu, mx0, 2));
            mx1 = fmaxf(mx1, __shfl_xor_sync(0xffffffffu, mx1, 1));
            mx1 = fmaxf(mx1, __shfl_xor_sync(0xffffffffu, mx1, 2));
            float mn0 = fmaxf(m[mt][0], mx0), mn1 = fmaxf(m[mt][1], mx1);
            alpha[mt][0] = __expf(m[mt][0] - mn0);
            alpha[mt][1] = __expf(m[mt][1] - mn1);
            m[mt][0] = mn0; m[mt][1] = mn1;
            float ps0 = 0.f, ps1 = 0.f;
            int r = wq + (mt << 4) + gid;
#pragma unroll
            for (int nt = 0; nt < 4; ++nt) {
                float px = __expf(s[mt][nt].x - mn0), py = __expf(s[mt][nt].y - mn0);
                float pz = __expf(s[mt][nt].z - mn1), pw = __expf(s[mt][nt].w - mn1);
                ps0 += px + py; ps1 += pz + pw;
                int c = (nt << 3) + (tig << 1);
                *(float2*)&Ps[r][c]     = make_float2(to_tf32(px), to_tf32(py));
                *(float2*)&Ps[r + 8][c] = make_float2(to_tf32(pz), to_tf32(pw));
            }
            ps0 += __shfl_xor_sync(0xffffffffu, ps0, 1);
            ps0 += __shfl_xor_sync(0xffffffffu, ps0, 2);
            ps1 += __shfl_xor_sync(0xffffffffu, ps1, 1);
            ps1 += __shfl_xor_sync(0xffffffffu, ps1, 2);
            l[mt][0] = l[mt][0] * alpha[mt][0] + ps0;
            l[mt][1] = l[mt][1] * alpha[mt][1] + ps1;
        }
#pragma unroll
        for (int mt = 0; mt < 2; ++mt)
#pragma unroll
            for (int nt = 0; nt < 8; ++nt) {
                o[mt][nt].x *= alpha[mt][0]; o[mt][nt].y *= alpha[mt][0];
                o[mt][nt].z *= alpha[mt][1]; o[mt][nt].w *= alpha[mt][1];
            }
        __syncwarp();   // Ps rows are warp-private

        // ---- O += P * V  (32 rows x 64 d per warp) ----
#pragma unroll
        for (int ks = 0; ks < 4; ++ks) {
            const int kk = ks << 3;
            unsigned a[2][4], b[8][2];
#pragma unroll
            for (int mt = 0; mt < 2; ++mt) {
                int r = wq + (mt << 4) + gid;
                a[mt][0] = __float_as_uint(Ps[r][kk + tig]);
                a[mt][1] = __float_as_uint(Ps[r + 8][kk + tig]);
                a[mt][2] = __float_as_uint(Ps[r][kk + tig + 4]);
                a[mt][3] = __float_as_uint(Ps[r + 8][kk + tig + 4]);
            }
#pragma unroll
            for (int nt = 0; nt < 8; ++nt) {
                int c = (nt << 3) + gid;           // d index
                b[nt][0] = __float_as_uint(Vs[kk + tig][c]);
                b[nt][1] = __float_as_uint(Vs[kk + tig + 4][c]);
            }
#pragma unroll
            for (int mt = 0; mt < 2; ++mt)
#pragma unroll
                for (int nt = 0; nt < 8; ++nt)
                    mma8(o[mt][nt], a[mt], b[nt], o[mt][nt]);
        }

        if (nxt) {
            __syncthreads();     // all warps done reading Ks/Vs
#pragma unroll
            for (int p = 0; p < 4; ++p) {
                int r = kvr + (p << 3);
                *(float4*)&Ks[r][kvc] = cvt4(kreg[p]);
                *(float4*)&Vs[r][kvc] = cvt4(vreg[p]);
            }
            __syncthreads();
        }
    }

    // ---- final normalize + store ----
    const int bb = bh >> 3, h = bh & 7;
#pragma unroll
    for (int mt = 0; mt < 2; ++mt) {
        float inv0 = 1.f / l[mt][0], inv1 = 1.f / l[mt][1];
        int nr0 = q0 + wq + (mt << 4) + gid;
        float* base0 = g_cat + ((bb * N_ + nr0) * H_ + h) * 128;
        float* base1 = g_cat + ((bb * N_ + nr0 + 8) * H_ + h) * 128;
#pragma unroll
        for (int nt = 0; nt < 8; ++nt) {
            int d = (nt << 3) + (tig << 1);
            *(float2*)(base0 + d)
                = make_float2(o[mt][nt].x * inv0, o[mt][nt].y * inv0);
            *(float2*)(base1 + d)
                = make_float2(o[mt][nt].z * inv1, o[mt][nt].w * inv1);
        }
    }
}

// ---------------------------------------------------------------------------
// Kernel 4: out = g_cat[4096,1024] @ W_out[1024,512] + b_out (tf32 MMA,
// 128x128 tile, double-buffered).  [proven config]
// ---------------------------------------------------------------------------
__global__ __launch_bounds__(256) void k_gemm_out(const float* __restrict__ W,
                                                  const float* __restrict__ bias,
                                                  float* __restrict__ out)
{
    __shared__ float As[2][128][36];
    __shared__ float Bs[2][32][136];
    const int tid  = threadIdx.x;
    const int lane = tid & 31, warp = tid >> 5;
    const int gid  = lane >> 2, tig = lane & 3;
    const int row0 = blockIdx.y << 7, col0 = blockIdx.x << 7;
    const int wm = (warp & 3) << 5;
    const int wn = (warp >> 2) << 6;

    float4 acc[2][8];
#pragma unroll
    for (int i = 0; i < 2; ++i)
#pragma unroll
        for (int j = 0; j < 8; ++j) acc[i][j] = make_float4(0.f, 0.f, 0.f, 0.f);

    const int ar_ = tid >> 3, ac_ = (tid & 7) << 2;
    const int br_ = tid >> 5, bc_ = (tid & 31) << 2;

    float4 ra[4], rb[4];
#pragma unroll
    for (int p = 0; p < 4; ++p)
        ra[p] = *(const float4*)(g_cat + (row0 + ar_ + (p << 5)) * 1024 + ac_);
#pragma unroll
    for (int p = 0; p < 4; ++p)
        rb[p] = *(const float4*)(W + (br_ + (p << 3)) * 512 + col0 + bc_);
#pragma unroll
    for (int p = 0; p < 4; ++p)
        *(float4*)&As[0][ar_ + (p << 5)][ac_] = cvt4(ra[p]);
#pragma unroll
    for (int p = 0; p < 4; ++p)
        *(float4*)&Bs[0][br_ + (p << 3)][bc_] = cvt4(rb[p]);
    __syncthreads();

    int buf = 0;
    for (int k0 = 0; k0 < 1024; k0 += 32) {
        const bool nxt = (k0 + 32) < 1024;
        if (nxt) {
#pragma unroll
            for (int p = 0; p < 4; ++p)
                ra[p] = *(const float4*)(g_cat + (row0 + ar_ + (p << 5)) * 1024
                                         + k0 + 32 + ac_);
#pragma unroll
            for (int p = 0; p < 4; ++p)
                rb[p] = *(const float4*)(W + (k0 + 32 + br_ + (p << 3)) * 512
                                         + col0 + bc_);
        }
        float (*Ac)[36]  = As[buf];
        float (*Bc)[136] = Bs[buf];
#pragma unroll
        for (int ks = 0; ks < 4; ++ks) {
            const int kk = ks << 3;
            unsigned a[2][4], b[8][2];
#pragma unroll
            for (int mt = 0; mt < 2; ++mt) {
                int r = wm + (mt << 4) + gid;
                a[mt][0] = __float_as_uint(Ac[r][kk + tig]);
                a[mt][1] = __float_as_uint(Ac[r + 8][kk + tig]);
                a[mt][2] = __float_as_uint(Ac[r][kk + tig + 4]);
                a[mt][3] = __float_as_uint(Ac[r + 8][kk + tig + 4]);
            }
#pragma unroll
            for (int nt = 0; nt < 8; ++nt) {
                int c = wn + (nt << 3) + gid;
                b[nt][0] = __float_as_uint(Bc[kk + tig][c]);
                b[nt][1] = __float_as_uint(Bc[kk + tig + 4][c]);
            }
#pragma unroll
            for (int mt = 0; mt < 2; ++mt)
#pragma unroll
                for (int nt = 0; nt < 8; ++nt)
                    mma8(acc[mt][nt], a[mt], b[nt], acc[mt][nt]);
        }
        if (nxt) {
            float (*An)[36]  = As[buf ^ 1];
            float (*Bn)[136] = Bs[buf ^ 1];
#pragma unroll
            for (int p = 0; p < 4; ++p)
                *(float4*)&An[ar_ + (p << 5)][ac_] = cvt4(ra[p]);
#pragma unroll
            for (int p = 0; p < 4; ++p)
                *(float4*)&Bn[br_ + (p << 3)][bc_] = cvt4(rb[p]);
        }
        __syncthreads();
        buf ^= 1;
    }

#pragma unroll
    for (int mt = 0; mt < 2; ++mt) {
        int gr0 = row0 + wm + (mt << 4) + gid;
        int gr1 = gr0 + 8;
#pragma unroll
        for (int nt = 0; nt < 8; ++nt) {
            int gc = col0 + wn + (nt << 3) + (tig << 1);
            float2 bv = *(const float2*)(bias + gc);
            *(float2*)(out + gr0 * 512 + gc)
                = make_float2(acc[mt][nt].x + bv.x, acc[mt][nt].y + bv.y);
            *(float2*)(out + gr1 * 512 + gc)
                = make_float2(acc[mt][nt].z + bv.x, acc[mt][nt].w + bv.y);
        }
    }
}

// ---------------------------------------------------------------------------
extern "C" void kernel_launch(void* const* d_in, const int* in_sizes, int n_in,
                              void* d_out, int out_size)
{
    (void)in_sizes; (void)n_in; (void)out_size;
    const float* x     = (const float*)d_in[0];
    const float* W_qkv = (const float*)d_in[1];
    const float* W_out = (const float*)d_in[2];
    const float* b_out = (const float*)d_in[3];
    float* out = (float*)d_out;

    k_gemm_qkv <<<dim3(16, 32), 256>>>(x, W_qkv);  // qkvt projection (tf32)
    k_attn_scan<<<320, 128>>>();                   // attn1 + attn2 (merged)
    k_gemm_out <<<dim3(4, 32), 256>>>(W_out, b_out, out);
}